// round 12
// baseline (speedup 1.0000x reference)
#include <cuda_runtime.h>
#include <cuda_bf16.h>
#include <math.h>
#include <stdint.h>

// Problem constants
#define BB 64
#define TT 256
#define DD 512
#define HH 1024         // H1 == H2
#define G4 4096         // 4*H
#define OO 512
#define MTOT (BB*TT)    // 16384

typedef unsigned long long ull;

// ---------------------------------------------------------------------------
// f32x2 packed-FMA helpers (sm_103a FFMA2) — used by the xz GEMM
// ---------------------------------------------------------------------------
__device__ __forceinline__ void ffma2(ull& d, ull a, ull b) {
    asm("fma.rn.f32x2 %0, %1, %2, %0;" : "+l"(d) : "l"(a), "l"(b));
}
__device__ __forceinline__ ull pack_dup(float x) {
    ull r; asm("mov.b64 %0, {%1, %1};" : "=l"(r) : "f"(x)); return r;
}
__device__ __forceinline__ ull pack2(float lo, float hi) {
    ull r; asm("mov.b64 %0, {%1, %2};" : "=l"(r) : "f"(lo), "f"(hi)); return r;
}
__device__ __forceinline__ float lo_f(ull v) { return __uint_as_float((unsigned)(v & 0xFFFFFFFFull)); }
__device__ __forceinline__ float hi_f(ull v) { return __uint_as_float((unsigned)(v >> 32)); }

// ---------------------------------------------------------------------------
// bf16 split helpers
// ---------------------------------------------------------------------------
__device__ __forceinline__ unsigned pk_bf(float a, float b) {
    unsigned short ua = __bfloat16_as_ushort(__float2bfloat16_rn(a));
    unsigned short ub = __bfloat16_as_ushort(__float2bfloat16_rn(b));
    return (unsigned)ua | ((unsigned)ub << 16);
}
__device__ __forceinline__ float bf_res(float x) {
    return x - __bfloat162float(__float2bfloat16_rn(x));
}

// mma.sync m16n8k16 bf16 (baseline PTX, sm_80+, valid on compute_103)
__device__ __forceinline__ void mma_bf16(float* d,
                                         uint32_t a0, uint32_t a1, uint32_t a2, uint32_t a3,
                                         uint32_t b0, uint32_t b1) {
    asm volatile(
        "mma.sync.aligned.m16n8k16.row.col.f32.bf16.bf16.f32 "
        "{%0,%1,%2,%3}, {%4,%5,%6,%7}, {%8,%9}, {%0,%1,%2,%3};"
        : "+f"(d[0]), "+f"(d[1]), "+f"(d[2]), "+f"(d[3])
        : "r"(a0), "r"(a1), "r"(a2), "r"(a3), "r"(b0), "r"(b1));
}

// cp.async (sm_80 PTX) helpers
__device__ __forceinline__ void cp16(uint32_t dst, const void* src) {
    asm volatile("cp.async.cg.shared.global [%0], [%1], 16;"
                 :: "r"(dst), "l"(src) : "memory");
}
#define CP_COMMIT() asm volatile("cp.async.commit_group;" ::: "memory")
#define CP_WAIT2()  asm volatile("cp.async.wait_group 2;" ::: "memory")

__device__ __forceinline__ uint32_t smem_u32(const void* p) {
    uint32_t a;
    asm("{ .reg .u64 t; cvta.to.shared.u64 t, %1; cvt.u32.u64 %0, t; }" : "=r"(a) : "l"(p));
    return a;
}

// ---------------------------------------------------------------------------
// Static device scratch
// ---------------------------------------------------------------------------
__device__ float g_xz[(size_t)MTOT * G4];     // 256 MB  z-pre (natural layout)
__device__ float g_seq1[(size_t)MTOT * HH];   // 64 MB   layer-1 h sequence
__device__ __nv_bfloat16 g_hhi[2][BB * HH];   // h hi plane, ping-pong
__device__ __nv_bfloat16 g_hlo[2][BB * HH];   // h lo (residual) plane
__device__ unsigned g_bar8[8];                // split grid-barrier counters

__global__ void zero_hc()
{
    int idx = blockIdx.x * blockDim.x + threadIdx.x;
    if (idx < BB * HH) {
        g_hhi[0][idx] = __float2bfloat16(0.f);
        g_hlo[0][idx] = __float2bfloat16(0.f);
    }
    if (idx < 8) g_bar8[idx] = 0u;
}

// ---------------------------------------------------------------------------
// Big GEMM (fp32 FFMA2, known good): g_xz[m][n] = sum_k A[m][k]*W[k][n] + b[n]
// ---------------------------------------------------------------------------
template<int MODE>
__global__ __launch_bounds__(256) void gemm_big(const float* __restrict__ Ain,
                                                const float* __restrict__ W,
                                                const float* __restrict__ bias,
                                                int K)
{
    __shared__ float As[2][16][136];
    __shared__ float Bs[2][16][136];

    const int tid  = threadIdx.x;
    const int tx   = tid & 15;
    const int ty   = tid >> 4;
    const int row0 = blockIdx.y * 128;
    const int n0   = blockIdx.x * 128;

    const float* A = (MODE == 0) ? Ain : (const float*)g_seq1;

    const int am0 = tid >> 2, aq0 = (tid & 3) * 4;
    const int am1 = (tid + 256) >> 2, aq1 = (tid & 3) * 4;
    const float *ap0, *ap1;
    {
        int mg0 = row0 + am0, mg1 = row0 + am1;
        if (MODE == 0) {
            ap0 = A + ((size_t)((mg0 & 63) * TT + (mg0 >> 6))) * DD;
            ap1 = A + ((size_t)((mg1 & 63) * TT + (mg1 >> 6))) * DD;
        } else {
            ap0 = A + (size_t)mg0 * K;
            ap1 = A + (size_t)mg1 * K;
        }
    }
    const int bk0 = tid >> 5, bq0 = (tid & 31) * 4;
    const int bk1 = (tid + 256) >> 5, bq1 = (tid & 31) * 4;

    ull acc[8][4];
    {
        float b0 = bias[n0 + tx * 4 + 0], b1 = bias[n0 + tx * 4 + 1];
        float b2 = bias[n0 + tx * 4 + 2], b3 = bias[n0 + tx * 4 + 3];
        float b4 = bias[n0 + 64 + tx * 4 + 0], b5 = bias[n0 + 64 + tx * 4 + 1];
        float b6 = bias[n0 + 64 + tx * 4 + 2], b7 = bias[n0 + 64 + tx * 4 + 3];
        ull p0 = pack2(b0, b1), p1 = pack2(b2, b3), p2 = pack2(b4, b5), p3 = pack2(b6, b7);
#pragma unroll
        for (int r = 0; r < 8; r++) { acc[r][0] = p0; acc[r][1] = p1; acc[r][2] = p2; acc[r][3] = p3; }
    }

    float4 pa0 = *(const float4*)(ap0 + aq0);
    float4 pa1 = *(const float4*)(ap1 + aq1);
    float4 pb0 = *(const float4*)(W + (size_t)bk0 * G4 + n0 + bq0);
    float4 pb1 = *(const float4*)(W + (size_t)bk1 * G4 + n0 + bq1);
    As[0][aq0 + 0][am0] = pa0.x; As[0][aq0 + 1][am0] = pa0.y;
    As[0][aq0 + 2][am0] = pa0.z; As[0][aq0 + 3][am0] = pa0.w;
    As[0][aq1 + 0][am1] = pa1.x; As[0][aq1 + 1][am1] = pa1.y;
    As[0][aq1 + 2][am1] = pa1.z; As[0][aq1 + 3][am1] = pa1.w;
    *(float4*)&Bs[0][bk0][bq0] = pb0;
    *(float4*)&Bs[0][bk1][bq1] = pb1;
    __syncthreads();

    int buf = 0;
    for (int k0 = 0; k0 < K; k0 += 16) {
        const bool more = (k0 + 16) < K;
        if (more) {
            pa0 = *(const float4*)(ap0 + k0 + 16 + aq0);
            pa1 = *(const float4*)(ap1 + k0 + 16 + aq1);
            pb0 = *(const float4*)(W + (size_t)(k0 + 16 + bk0) * G4 + n0 + bq0);
            pb1 = *(const float4*)(W + (size_t)(k0 + 16 + bk1) * G4 + n0 + bq1);
        }
#pragma unroll
        for (int k = 0; k < 16; k++) {
            ulonglong2 blo = *(const ulonglong2*)&Bs[buf][k][tx * 4];
            ulonglong2 bhi = *(const ulonglong2*)&Bs[buf][k][64 + tx * 4];
            float a[8];
            *(float4*)&a[0] = *(const float4*)&As[buf][k][ty * 4];
            *(float4*)&a[4] = *(const float4*)&As[buf][k][64 + ty * 4];
#pragma unroll
            for (int r = 0; r < 8; r++) {
                ull ap = pack_dup(a[r]);
                ffma2(acc[r][0], ap, blo.x);
                ffma2(acc[r][1], ap, blo.y);
                ffma2(acc[r][2], ap, bhi.x);
                ffma2(acc[r][3], ap, bhi.y);
            }
        }
        if (more) {
            int nb = buf ^ 1;
            As[nb][aq0 + 0][am0] = pa0.x; As[nb][aq0 + 1][am0] = pa0.y;
            As[nb][aq0 + 2][am0] = pa0.z; As[nb][aq0 + 3][am0] = pa0.w;
            As[nb][aq1 + 0][am1] = pa1.x; As[nb][aq1 + 1][am1] = pa1.y;
            As[nb][aq1 + 2][am1] = pa1.z; As[nb][aq1 + 3][am1] = pa1.w;
            *(float4*)&Bs[nb][bk0][bq0] = pb0;
            *(float4*)&Bs[nb][bk1][bq1] = pb1;
        }
        __syncthreads();
        buf ^= 1;
    }

#pragma unroll
    for (int r = 0; r < 8; r++) {
        int m = row0 + ((r < 4) ? (ty * 4 + r) : (64 + ty * 4 + (r - 4)));
        float* op = g_xz + (size_t)m * G4 + n0;
        float4 v0 = make_float4(lo_f(acc[r][0]), hi_f(acc[r][0]),
                                lo_f(acc[r][1]), hi_f(acc[r][1]));
        float4 v1 = make_float4(lo_f(acc[r][2]), hi_f(acc[r][2]),
                                lo_f(acc[r][3]), hi_f(acc[r][3]));
        *(float4*)(op + tx * 4)      = v0;
        *(float4*)(op + 64 + tx * 4) = v1;
    }
}

// ---------------------------------------------------------------------------
// Persistent mma.sync recurrence v3: WARP-LOCAL staging, no mainloop barriers.
// 128 CTAs x 512 thr (16 warps), 1 CTA/SM. Warp (mi=w&3, ks=w>>2) owns a
// disjoint 16-row x 16-k A-tile per chunk -> it cp.asyncs exactly what it
// consumes into its private smem region (16 rows x 48B stride, hi+lo), and
// synchronizes only via its own cp.async.wait_group. 4 stages in flight.
// Chunk sync cost per step: 0 CTA barriers in mainloop (was 16), 2 in epilogue.
// Z = h @ Uslice via 2-term bf16 split; k-split reduced through smem overlay;
// gates with c in registers; producer-side bf16 hi/lo h planes (ping-pong);
// 8-counter grid barrier between steps.
// ---------------------------------------------------------------------------
#define OFF_UB      0
#define OFF_A       131072
#define STAGE_BYTES 24576                 // 16 warps x 1536 B
#define WARP_BYTES  1536                  // hi 768 (16 rows x 48B) + lo 768
#define SMEM_BYTES  (131072 + 4 * 24576)  // 229,376 B (= 224 KB)

__global__ __launch_bounds__(512) void lstm_layer_mma(const float* __restrict__ U,
                                                      int layer)
{
    extern __shared__ char smc[];
    const int tid  = threadIdx.x;
    const int lane = tid & 31;
    const int w    = tid >> 5;          // 0..15
    const int mi   = w & 3;             // m-tile (16 rows)
    const int ks   = w >> 2;            // k-split 0..3
    const int u0   = blockIdx.x * 8;

    // ---- pack U slice into fragment-order smem, hi/lo interleaved 16B ----
    // slot s = (kstep(64)*4 + nt)*32 + lane : {bh.x,bh.y,bl.x,bl.y}
    for (int s = tid; s < 8192; s += 512) {
        int ln  = s & 31;
        int nt  = (s >> 5) & 3;
        int kst = s >> 7;
        int gc  = (nt << 10) + u0 + (ln >> 2);
        int k0  = kst * 16 + (ln & 3) * 2;
        float v0 = U[(size_t)(k0    ) * G4 + gc];
        float v1 = U[(size_t)(k0 + 1) * G4 + gc];
        float v8 = U[(size_t)(k0 + 8) * G4 + gc];
        float v9 = U[(size_t)(k0 + 9) * G4 + gc];
        *(uint4*)(smc + OFF_UB + (size_t)s * 16) =
            make_uint4(pk_bf(v0, v1), pk_bf(v8, v9),
                       pk_bf(bf_res(v0), bf_res(v1)), pk_bf(bf_res(v8), bf_res(v9)));
    }

    const uint32_t smbase = smem_u32(smc);

    // warp-local staging: lane -> (row rr = lane>>1, 16B seg ss = lane&1),
    // one cp16 to the hi plane and one to the lo plane per chunk.
    const int rr = lane >> 1, ss = lane & 1;
    const uint32_t st_d0 = smbase + OFF_A + w * WARP_BYTES + rr * 48 + ss * 16;        // hi
    const uint32_t st_d1 = st_d0 + 768;                                                 // lo
    const int src_off = (mi * 16 + rr) * HH + ks * 16 + ss * 8;   // element offset

    // A-fragment read offsets within this warp's region (48B row stride:
    // word = row*12 + (lane&3) -> all 32 banks distinct, conflict-free)
    const int fr_off = (lane >> 2) * 48 + (lane & 3) * 4;

    float creg = 0.f;                   // cell state: thread owns (em, ej)
    const int em = tid >> 3, ej = tid & 7;

    float* ZR = (float*)(smc + OFF_A);  // epilogue overlay: [ks][64][34] fp32
    volatile unsigned* vb = g_bar8;

    __syncthreads();

    for (int t = 0; t < TT; t++) {
        const __nv_bfloat16* phi = g_hhi[t & 1] + src_off;
        const __nv_bfloat16* plo = g_hlo[t & 1] + src_off;

        // prefetch xz (used only in epilogue)
        const float* xzp = g_xz + ((size_t)t * BB + em) * G4 + u0 + ej;
        float x0 = __ldg(xzp);
        float x1 = __ldg(xzp + 1024);
        float x2 = __ldg(xzp + 2048);
        float x3 = __ldg(xzp + 3072);

        // pipeline prologue: issue chunks 0..2 (warp-local)
#pragma unroll
        for (int pc = 0; pc < 3; pc++) {
            cp16(st_d0 + pc * STAGE_BYTES, phi + pc * 64);
            cp16(st_d1 + pc * STAGE_BYTES, plo + pc * 64);
            CP_COMMIT();
        }

        float d[4][4];
#pragma unroll
        for (int nt = 0; nt < 4; nt++)
#pragma unroll
            for (int i = 0; i < 4; i++) d[nt][i] = 0.f;

        for (int c = 0; c < 16; c++) {
            CP_WAIT2();                       // warp-local: chunk c's group done

            const char* ab = smc + OFF_A + (c & 3) * STAGE_BYTES + w * WARP_BYTES + fr_off;
            uint32_t ah0 = *(const uint32_t*)(ab);
            uint32_t ah1 = *(const uint32_t*)(ab + 384);         // +8 rows
            uint32_t ah2 = *(const uint32_t*)(ab + 16);          // +8 k (seg 1)
            uint32_t ah3 = *(const uint32_t*)(ab + 400);
            uint32_t al0 = *(const uint32_t*)(ab + 768);
            uint32_t al1 = *(const uint32_t*)(ab + 768 + 384);
            uint32_t al2 = *(const uint32_t*)(ab + 768 + 16);
            uint32_t al3 = *(const uint32_t*)(ab + 768 + 400);
#pragma unroll
            for (int nt = 0; nt < 4; nt++) {
                uint4 bv = *(const uint4*)(smc + OFF_UB +
                    (size_t)((((c * 4 + ks) * 4 + nt) * 32 + lane) * 16));
                mma_bf16(d[nt], ah0, ah1, ah2, ah3, bv.x, bv.y);
                mma_bf16(d[nt], ah0, ah1, ah2, ah3, bv.z, bv.w);
                mma_bf16(d[nt], al0, al1, al2, al3, bv.x, bv.y);
            }

            if (c < 13) {                     // issue chunk c+3 into stage (c+3)&3
                cp16(st_d0 + ((c + 3) & 3) * STAGE_BYTES, phi + (c + 3) * 64);
                cp16(st_d1 + ((c + 3) & 3) * STAGE_BYTES, plo + (c + 3) * 64);
            }
            CP_COMMIT();                      // empty groups keep the count uniform
        }
        __syncthreads();    // all warps done with A stages before ZR overlays them

        // ---- k-split reduction over smem overlay ----
        {
            int zw = ks * 2176 + (mi * 16 + (lane >> 2)) * 34 + (lane & 3) * 2;
#pragma unroll
            for (int nt = 0; nt < 4; nt++) {
                *(float2*)&ZR[zw + nt * 8]          = make_float2(d[nt][0], d[nt][1]);
                *(float2*)&ZR[zw + nt * 8 + 8 * 34] = make_float2(d[nt][2], d[nt][3]);
            }
        }
        __syncthreads();
        {
            float z[4];
#pragma unroll
            for (int g = 0; g < 4; g++) {
                int zc = em * 34 + g * 8 + ej;
                z[g] = ZR[zc] + ZR[zc + 2176] + ZR[zc + 4352] + ZR[zc + 6528];
            }
            float zi = z[0] + x0;
            float zf = z[1] + x1;
            float zg = z[2] + x2;
            float zo = z[3] + x3;
            float si = 1.f / (1.f + __expf(-zi));
            float sf = 1.f / (1.f + __expf(-zf));
            float so = 1.f / (1.f + __expf(-zo));
            float tg = tanhf(zg);
            float cn = sf * creg + si * tg;
            creg = cn;
            float hn = so * tanhf(cn);
            __nv_bfloat16 hb = __float2bfloat16_rn(hn);
            __nv_bfloat16 lb = __float2bfloat16_rn(hn - __bfloat162float(hb));
            int idx = em * HH + u0 + ej;
            g_hhi[(t + 1) & 1][idx] = hb;
            g_hlo[(t + 1) & 1][idx] = lb;
            if (layer == 0)
                g_seq1[(size_t)t * BB * HH + idx] = hn;
        }

        // ---- grid barrier (8 split counters) ----
        if (t < TT - 1) {
            __threadfence();
            __syncthreads();
            if (tid == 0) atomicAdd(&g_bar8[blockIdx.x & 7], 1u);
            unsigned target = (unsigned)(t + 1) * 16u;
            if (tid < 8) { while (vb[tid] < target) { } }
            __syncthreads();
        }
    }
}

// ---------------------------------------------------------------------------
// Final dense: h_last reconstructed from hi+lo planes (buf 0, T even)
// ---------------------------------------------------------------------------
__global__ void dense_out(const float* __restrict__ Wd, const float* __restrict__ bd,
                          float* __restrict__ out)
{
    int b = blockIdx.x;
    int o = threadIdx.x;
    const __nv_bfloat16* hi = g_hhi[0] + (size_t)b * HH;
    const __nv_bfloat16* lo = g_hlo[0] + (size_t)b * HH;
    float acc = bd[o];
#pragma unroll 8
    for (int k = 0; k < HH; k++) {
        float h = __bfloat162float(hi[k]) + __bfloat162float(lo[k]);
        acc += h * Wd[(size_t)k * OO + o];
    }
    out[(size_t)b * OO + o] = acc;
}

// ---------------------------------------------------------------------------
// Launch sequence (recurrence at index 3 for the ncu capture)
// ---------------------------------------------------------------------------
extern "C" void kernel_launch(void* const* d_in, const int* in_sizes, int n_in,
                              void* d_out, int out_size)
{
    const float* x  = (const float*)d_in[0];
    const float* W1 = (const float*)d_in[1];
    const float* U1 = (const float*)d_in[2];
    const float* b1 = (const float*)d_in[3];
    const float* W2 = (const float*)d_in[4];
    const float* U2 = (const float*)d_in[5];
    const float* b2 = (const float*)d_in[6];
    const float* Wd = (const float*)d_in[7];
    const float* bd = (const float*)d_in[8];
    float* out = (float*)d_out;

    cudaFuncSetAttribute(lstm_layer_mma,
                         cudaFuncAttributeMaxDynamicSharedMemorySize, SMEM_BYTES);

    dim3 gemm_grid(G4 / 128, MTOT / 128);

    // ---- Layer 1 ----
    gemm_big<0><<<gemm_grid, 256>>>(x, W1, b1, DD);          // 0
    zero_hc<<<(BB * HH + 255) / 256, 256>>>();               // 1
    zero_hc<<<(BB * HH + 255) / 256, 256>>>();               // 2 (spacer)
    lstm_layer_mma<<<128, 512, SMEM_BYTES>>>(U1, 0);         // 3 <- profiled

    // ---- Layer 2 ----
    gemm_big<1><<<gemm_grid, 256>>>(nullptr, W2, b2, HH);    // 4
    zero_hc<<<(BB * HH + 255) / 256, 256>>>();               // 5
    lstm_layer_mma<<<128, 512, SMEM_BYTES>>>(U2, 1);         // 6

    // ---- Dense head ----
    dense_out<<<BB, OO>>>(Wd, bd, out);                      // 7
}

// round 15
// speedup vs baseline: 1.0934x; 1.0934x over previous
#include <cuda_runtime.h>
#include <cuda_bf16.h>
#include <math.h>
#include <stdint.h>

// Problem constants
#define BB 64
#define TT 256
#define DD 512
#define HH 1024         // H1 == H2
#define G4 4096         // 4*H
#define OO 512
#define MTOT (BB*TT)    // 16384

// ---------------------------------------------------------------------------
// bf16 split helpers
// ---------------------------------------------------------------------------
__device__ __forceinline__ unsigned pk_bf(float a, float b) {
    unsigned short ua = __bfloat16_as_ushort(__float2bfloat16_rn(a));
    unsigned short ub = __bfloat16_as_ushort(__float2bfloat16_rn(b));
    return (unsigned)ua | ((unsigned)ub << 16);
}
__device__ __forceinline__ float bf_res(float x) {
    return x - __bfloat162float(__float2bfloat16_rn(x));
}

// mma.sync m16n8k16 bf16 (baseline PTX, sm_80+, valid on compute_103)
__device__ __forceinline__ void mma_bf16(float* d,
                                         uint32_t a0, uint32_t a1, uint32_t a2, uint32_t a3,
                                         uint32_t b0, uint32_t b1) {
    asm volatile(
        "mma.sync.aligned.m16n8k16.row.col.f32.bf16.bf16.f32 "
        "{%0,%1,%2,%3}, {%4,%5,%6,%7}, {%8,%9}, {%0,%1,%2,%3};"
        : "+f"(d[0]), "+f"(d[1]), "+f"(d[2]), "+f"(d[3])
        : "r"(a0), "r"(a1), "r"(a2), "r"(a3), "r"(b0), "r"(b1));
}

// cp.async (sm_80 PTX) helpers — used by the recurrence only
__device__ __forceinline__ void cp16(uint32_t dst, const void* src) {
    asm volatile("cp.async.cg.shared.global [%0], [%1], 16;"
                 :: "r"(dst), "l"(src) : "memory");
}
#define CP_COMMIT() asm volatile("cp.async.commit_group;" ::: "memory")
#define CP_WAIT2()  asm volatile("cp.async.wait_group 2;" ::: "memory")

__device__ __forceinline__ uint32_t smem_u32(const void* p) {
    uint32_t a;
    asm("{ .reg .u64 t; cvta.to.shared.u64 t, %1; cvt.u32.u64 %0, t; }" : "=r"(a) : "l"(p));
    return a;
}

// ---------------------------------------------------------------------------
// Static device scratch. RULE (R13/R14 lesson): __device__ symbols are
// resolved ONLY inside device code; host passes nullptr + a mode flag.
// ---------------------------------------------------------------------------
__device__ float g_xz[(size_t)MTOT * G4];           // 256 MB  z-pre (natural layout)
__device__ float g_seq1[(size_t)MTOT * HH];         // 64 MB   layer-1 h sequence (fp32)
__device__ __align__(16) uint4 g_Bw[(size_t)512 * 64 * 32];  // 16 MB packed W slots
__device__ __nv_bfloat16 g_hhi[2][BB * HH];         // h hi plane, ping-pong
__device__ __nv_bfloat16 g_hlo[2][BB * HH];         // h lo (residual) plane
__device__ unsigned g_bar8[8];                      // split grid-barrier counters

__global__ void zero_hc()
{
    int idx = blockIdx.x * blockDim.x + threadIdx.x;
    if (idx < BB * HH) {
        g_hhi[0][idx] = __float2bfloat16(0.f);
        g_hlo[0][idx] = __float2bfloat16(0.f);
    }
    if (idx < 8) g_bar8[idx] = 0u;
}

// ---------------------------------------------------------------------------
// pack_W: W fp32 [k][4096] -> B-fragment slots {bh0,bh1,bl0,bl1} (16 B/slot),
// slot index = (ntile*KS + kstep)*32 + lane. Identical layout to the
// recurrence's proven smem U pack. n = ntile*8 + lane>>2,
// k0 = kstep*16 + (lane&3)*2; bh0=(k0,k0+1), bh1=(k0+8,k0+9).
// ---------------------------------------------------------------------------
__global__ void pack_W(const float* __restrict__ W, int KS)
{
    size_t s = (size_t)blockIdx.x * 256 + threadIdx.x;
    if (s >= (size_t)512 * KS * 32) return;
    int lane = (int)(s & 31);
    size_t nk = s >> 5;                   // ntile*KS + kstep
    int kstep = (int)(nk % KS);
    int ntile = (int)(nk / KS);
    int n  = ntile * 8 + (lane >> 2);
    int k0 = kstep * 16 + (lane & 3) * 2;
    float v0 = W[(size_t)(k0    ) * G4 + n];
    float v1 = W[(size_t)(k0 + 1) * G4 + n];
    float v8 = W[(size_t)(k0 + 8) * G4 + n];
    float v9 = W[(size_t)(k0 + 9) * G4 + n];
    g_Bw[s] = make_uint4(pk_bf(v0, v1), pk_bf(v8, v9),
                         pk_bf(bf_res(v0), bf_res(v1)), pk_bf(bf_res(v8), bf_res(v9)));
}

// ---------------------------------------------------------------------------
// gemm_mma_direct: g_xz[m][n] = sum_k A[m][k]*W[k][n] + bias[n] on mma.sync,
// 2-term bf16 split (hi*bh + hi*bl + lo*bh). NO smem, NO barriers:
//  - A fragments converted in-registers from fp32 rows (LDG.64 pairs along k).
//  - B fragments read as packed slots from g_Bw via coalesced LDG.128.
// 512 thr, tile 128m x 128n per CTA: warp (mw=w&3, nw=w>>2) owns 32m x 32n.
// mode 0: A = Ain = x [b][t][d] (K=512); mode 1: A = g_seq1 (device-resolved,
// row-major, K=1024) — Ain is ignored (host passes nullptr).
// ---------------------------------------------------------------------------
__global__ __launch_bounds__(512) void gemm_mma_direct(const float* __restrict__ Ain,
                                                       const float* __restrict__ bias,
                                                       int KS, int mode)
{
    const int tid  = threadIdx.x;
    const int lane = tid & 31;
    const int w    = tid >> 5;
    const int mw   = w & 3;
    const int nw   = w >> 2;
    const int nblk = blockIdx.x;          // 0..31
    const int mblk = blockIdx.y;          // 0..127
    const int K    = KS << 4;

    // resolve A base IN DEVICE CODE (never pass __device__ symbols from host)
    const float* Abase = (mode == 0) ? Ain : (const float*)g_seq1;

    // A row pointers: [mt2][h] -> row = base + mt2*16 + h*8 + lane>>2
    const float* ar[2][2];
#pragma unroll
    for (int mt2 = 0; mt2 < 2; mt2++)
#pragma unroll
        for (int h = 0; h < 2; h++) {
            int m = mblk * 128 + mw * 32 + mt2 * 16 + h * 8 + (lane >> 2);
            ar[mt2][h] = (mode == 0)
                ? Abase + ((size_t)((m & 63) * TT + (m >> 6))) * DD
                : Abase + (size_t)m * K;
        }
    const int kb = (lane & 3) * 2;

    float acc[2][4][4];
#pragma unroll
    for (int a = 0; a < 2; a++)
#pragma unroll
        for (int b = 0; b < 4; b++)
#pragma unroll
            for (int i = 0; i < 4; i++) acc[a][b][i] = 0.f;

    for (int kst = 0; kst < KS; kst++) {
        const int k0 = kst * 16 + kb;

        uint32_t ah[2][4], al[2][4];
#pragma unroll
        for (int mt2 = 0; mt2 < 2; mt2++) {
            float2 v0 = *(const float2*)(ar[mt2][0] + k0);        // (r,   k0..k0+1)
            float2 v1 = *(const float2*)(ar[mt2][1] + k0);        // (r+8, k0..k0+1)
            float2 v2 = *(const float2*)(ar[mt2][0] + k0 + 8);    // (r,   k0+8..9)
            float2 v3 = *(const float2*)(ar[mt2][1] + k0 + 8);    // (r+8, k0+8..9)
            ah[mt2][0] = pk_bf(v0.x, v0.y);
            ah[mt2][1] = pk_bf(v1.x, v1.y);
            ah[mt2][2] = pk_bf(v2.x, v2.y);
            ah[mt2][3] = pk_bf(v3.x, v3.y);
            al[mt2][0] = pk_bf(bf_res(v0.x), bf_res(v0.y));
            al[mt2][1] = pk_bf(bf_res(v1.x), bf_res(v1.y));
            al[mt2][2] = pk_bf(bf_res(v2.x), bf_res(v2.y));
            al[mt2][3] = pk_bf(bf_res(v3.x), bf_res(v3.y));
        }

#pragma unroll
        for (int nt4 = 0; nt4 < 4; nt4++) {
            int ntile = nblk * 16 + nw * 4 + nt4;
            uint4 bv = __ldg(&g_Bw[((size_t)ntile * KS + kst) * 32 + lane]);
#pragma unroll
            for (int mt2 = 0; mt2 < 2; mt2++) {
                mma_bf16(acc[mt2][nt4], ah[mt2][0], ah[mt2][1], ah[mt2][2], ah[mt2][3], bv.x, bv.y);
                mma_bf16(acc[mt2][nt4], ah[mt2][0], ah[mt2][1], ah[mt2][2], ah[mt2][3], bv.z, bv.w);
                mma_bf16(acc[mt2][nt4], al[mt2][0], al[mt2][1], al[mt2][2], al[mt2][3], bv.x, bv.y);
            }
        }
    }

    // epilogue: bias + fp32 store (D fragment: d0,d1 = row; d2,d3 = row+8)
#pragma unroll
    for (int mt2 = 0; mt2 < 2; mt2++) {
        int row = mblk * 128 + mw * 32 + mt2 * 16 + (lane >> 2);
#pragma unroll
        for (int nt4 = 0; nt4 < 4; nt4++) {
            int col = nblk * 128 + nw * 32 + nt4 * 8 + (lane & 3) * 2;
            float b0 = __ldg(bias + col);
            float b1 = __ldg(bias + col + 1);
            *(float2*)(g_xz + (size_t)row * G4 + col) =
                make_float2(acc[mt2][nt4][0] + b0, acc[mt2][nt4][1] + b1);
            *(float2*)(g_xz + (size_t)(row + 8) * G4 + col) =
                make_float2(acc[mt2][nt4][2] + b0, acc[mt2][nt4][3] + b1);
        }
    }
}

// ---------------------------------------------------------------------------
// Persistent mma.sync recurrence — R11 version VERBATIM (best measured,
// 9386.7us): CTA-wide coalesced cp.async staging, 4 stages, producer-side
// bf16 hi/lo h planes, fp32 seq1 stores for layer 0, 8-counter grid barrier.
// ---------------------------------------------------------------------------
#define OFF_UB     0
#define OFF_A      131072                // 4 bufs x (hi 9216 + lo 9216)
#define A_PLANE    9216
#define A_BUF      18432
#define SMEM_BYTES (131072 + 4 * 18432)  // 204,800 B

__global__ __launch_bounds__(512) void lstm_layer_mma(const float* __restrict__ U,
                                                      int layer)
{
    extern __shared__ char smc[];
    const int tid  = threadIdx.x;
    const int lane = tid & 31;
    const int w    = tid >> 5;          // 0..15
    const int mi   = w & 3;             // m-tile (16 rows)
    const int ks   = w >> 2;            // k-split 0..3
    const int u0   = blockIdx.x * 8;

    // ---- pack U slice into fragment-order smem, hi/lo interleaved 16B ----
    for (int s = tid; s < 8192; s += 512) {
        int ln  = s & 31;
        int nt  = (s >> 5) & 3;
        int kst = s >> 7;
        int gc  = (nt << 10) + u0 + (ln >> 2);
        int k0  = kst * 16 + (ln & 3) * 2;
        float v0 = U[(size_t)(k0    ) * G4 + gc];
        float v1 = U[(size_t)(k0 + 1) * G4 + gc];
        float v8 = U[(size_t)(k0 + 8) * G4 + gc];
        float v9 = U[(size_t)(k0 + 9) * G4 + gc];
        *(uint4*)(smc + OFF_UB + (size_t)s * 16) =
            make_uint4(pk_bf(v0, v1), pk_bf(v8, v9),
                       pk_bf(bf_res(v0), bf_res(v1)), pk_bf(bf_res(v8), bf_res(v9)));
    }

    const int row8 = tid >> 3;
    const int kseg = tid & 7;
    const uint32_t smbase = smem_u32(smc);
    const uint32_t st_hi  = smbase + OFF_A + (uint32_t)row8 * 144 + kseg * 16;
    const int      goff   = row8 * HH + kseg * 8;

    const int a_off = ((mi * 16 + (lane >> 2)) * 72 + ks * 16 + (lane & 3) * 2) * 2;

    float creg = 0.f;
    const int em = tid >> 3, ej = tid & 7;

    float* ZR = (float*)(smc + OFF_A);
    volatile unsigned* vb = g_bar8;

    __syncthreads();

    for (int t = 0; t < TT; t++) {
        const __nv_bfloat16* phi = g_hhi[t & 1] + goff;
        const __nv_bfloat16* plo = g_hlo[t & 1] + goff;

        const float* xzp = g_xz + ((size_t)t * BB + em) * G4 + u0 + ej;
        float x0 = __ldg(xzp);
        float x1 = __ldg(xzp + 1024);
        float x2 = __ldg(xzp + 2048);
        float x3 = __ldg(xzp + 3072);

#pragma unroll
        for (int pc = 0; pc < 3; pc++) {
            cp16(st_hi + pc * A_BUF,           phi + pc * 64);
            cp16(st_hi + pc * A_BUF + A_PLANE, plo + pc * 64);
            CP_COMMIT();
        }

        float d[4][4];
#pragma unroll
        for (int nt = 0; nt < 4; nt++)
#pragma unroll
            for (int i = 0; i < 4; i++) d[nt][i] = 0.f;

        for (int c = 0; c < 16; c++) {
            CP_WAIT2();
            __syncthreads();

            const char* ab = smc + OFF_A + (c & 3) * A_BUF + a_off;
            uint32_t ah0 = *(const uint32_t*)(ab);
            uint32_t ah1 = *(const uint32_t*)(ab + 1152);
            uint32_t ah2 = *(const uint32_t*)(ab + 16);
            uint32_t ah3 = *(const uint32_t*)(ab + 1168);
            uint32_t al0 = *(const uint32_t*)(ab + A_PLANE);
            uint32_t al1 = *(const uint32_t*)(ab + A_PLANE + 1152);
            uint32_t al2 = *(const uint32_t*)(ab + A_PLANE + 16);
            uint32_t al3 = *(const uint32_t*)(ab + A_PLANE + 1168);
#pragma unroll
            for (int nt = 0; nt < 4; nt++) {
                uint4 bv = *(const uint4*)(smc + OFF_UB +
                    (size_t)((((c * 4 + ks) * 4 + nt) * 32 + lane) * 16));
                mma_bf16(d[nt], ah0, ah1, ah2, ah3, bv.x, bv.y);
                mma_bf16(d[nt], ah0, ah1, ah2, ah3, bv.z, bv.w);
                mma_bf16(d[nt], al0, al1, al2, al3, bv.x, bv.y);
            }

            if (c < 13) {
                cp16(st_hi + ((c + 3) & 3) * A_BUF,           phi + (c + 3) * 64);
                cp16(st_hi + ((c + 3) & 3) * A_BUF + A_PLANE, plo + (c + 3) * 64);
            }
            CP_COMMIT();
        }
        __syncthreads();

        {
            int zw = ks * 2176 + (mi * 16 + (lane >> 2)) * 34 + (lane & 3) * 2;
#pragma unroll
            for (int nt = 0; nt < 4; nt++) {
                *(float2*)&ZR[zw + nt * 8]          = make_float2(d[nt][0], d[nt][1]);
                *(float2*)&ZR[zw + nt * 8 + 8 * 34] = make_float2(d[nt][2], d[nt][3]);
            }
        }
        __syncthreads();
        {
            float z[4];
#pragma unroll
            for (int g = 0; g < 4; g++) {
                int zc = em * 34 + g * 8 + ej;
                z[g] = ZR[zc] + ZR[zc + 2176] + ZR[zc + 4352] + ZR[zc + 6528];
            }
            float zi = z[0] + x0;
            float zf = z[1] + x1;
            float zg = z[2] + x2;
            float zo = z[3] + x3;
            float si = 1.f / (1.f + __expf(-zi));
            float sf = 1.f / (1.f + __expf(-zf));
            float so = 1.f / (1.f + __expf(-zo));
            float tg = tanhf(zg);
            float cn = sf * creg + si * tg;
            creg = cn;
            float hn = so * tanhf(cn);
            __nv_bfloat16 hb = __float2bfloat16_rn(hn);
            __nv_bfloat16 lb = __float2bfloat16_rn(hn - __bfloat162float(hb));
            int idx = em * HH + u0 + ej;
            g_hhi[(t + 1) & 1][idx] = hb;
            g_hlo[(t + 1) & 1][idx] = lb;
            if (layer == 0)
                g_seq1[(size_t)t * BB * HH + idx] = hn;
        }

        if (t < TT - 1) {
            __threadfence();
            __syncthreads();
            if (tid == 0) atomicAdd(&g_bar8[blockIdx.x & 7], 1u);
            unsigned target = (unsigned)(t + 1) * 16u;
            if (tid < 8) { while (vb[tid] < target) { } }
            __syncthreads();
        }
    }
}

// ---------------------------------------------------------------------------
// Final dense: h_last reconstructed from hi+lo planes (buf 0, T even)
// ---------------------------------------------------------------------------
__global__ void dense_out(const float* __restrict__ Wd, const float* __restrict__ bd,
                          float* __restrict__ out)
{
    int b = blockIdx.x;
    int o = threadIdx.x;
    const __nv_bfloat16* hi = g_hhi[0] + (size_t)b * HH;
    const __nv_bfloat16* lo = g_hlo[0] + (size_t)b * HH;
    float acc = bd[o];
#pragma unroll 8
    for (int k = 0; k < HH; k++) {
        float h = __bfloat162float(hi[k]) + __bfloat162float(lo[k]);
        acc += h * Wd[(size_t)k * OO + o];
    }
    out[(size_t)b * OO + o] = acc;
}

// ---------------------------------------------------------------------------
// Launch sequence (gemm_mma_direct L1 at index 3 for the ncu capture).
// NOTE: __device__ symbols are never passed as arguments — mode flag instead.
// ---------------------------------------------------------------------------
extern "C" void kernel_launch(void* const* d_in, const int* in_sizes, int n_in,
                              void* d_out, int out_size)
{
    const float* x  = (const float*)d_in[0];
    const float* W1 = (const float*)d_in[1];
    const float* U1 = (const float*)d_in[2];
    const float* b1 = (const float*)d_in[3];
    const float* W2 = (const float*)d_in[4];
    const float* U2 = (const float*)d_in[5];
    const float* b2 = (const float*)d_in[6];
    const float* Wd = (const float*)d_in[7];
    const float* bd = (const float*)d_in[8];
    float* out = (float*)d_out;

    cudaFuncSetAttribute(lstm_layer_mma,
                         cudaFuncAttributeMaxDynamicSharedMemorySize, SMEM_BYTES);

    dim3 gg(32, 128);

    // ---- Layer 1 ----
    pack_W<<<(int)(((size_t)512 * 32 * 32 + 255) / 256), 256>>>(W1, 32);     // 0
    zero_hc<<<(BB * HH + 255) / 256, 256>>>();                               // 1
    zero_hc<<<(BB * HH + 255) / 256, 256>>>();                               // 2 (spacer)
    gemm_mma_direct<<<gg, 512>>>(x, b1, 32, 0);                              // 3 <- profiled
    lstm_layer_mma<<<128, 512, SMEM_BYTES>>>(U1, 0);                         // 4

    // ---- Layer 2 ----
    pack_W<<<(int)(((size_t)512 * 64 * 32 + 255) / 256), 256>>>(W2, 64);     // 5
    zero_hc<<<(BB * HH + 255) / 256, 256>>>();                               // 6
    gemm_mma_direct<<<gg, 512>>>(nullptr, b2, 64, 1);                        // 7
    lstm_layer_mma<<<128, 512, SMEM_BYTES>>>(U2, 1);                         // 8

    // ---- Dense head ----
    dense_out<<<BB, OO>>>(Wd, bd, out);                                      // 9
}

// round 16
// speedup vs baseline: 1.4370x; 1.3143x over previous
#include <cuda_runtime.h>
#include <cuda_bf16.h>
#include <math.h>
#include <stdint.h>

// Problem constants
#define BB 64
#define TT 256
#define DD 512
#define HH 1024         // H1 == H2
#define G4 4096         // 4*H
#define OO 512
#define MTOT (BB*TT)    // 16384

// ---------------------------------------------------------------------------
// bf16 split helpers
// ---------------------------------------------------------------------------
__device__ __forceinline__ unsigned pk_bf(float a, float b) {
    unsigned short ua = __bfloat16_as_ushort(__float2bfloat16_rn(a));
    unsigned short ub = __bfloat16_as_ushort(__float2bfloat16_rn(b));
    return (unsigned)ua | ((unsigned)ub << 16);
}
__device__ __forceinline__ float bf_res(float x) {
    return x - __bfloat162float(__float2bfloat16_rn(x));
}

// mma.sync m16n8k16 bf16 (baseline PTX, sm_80+, valid on compute_103)
__device__ __forceinline__ void mma_bf16(float* d,
                                         uint32_t a0, uint32_t a1, uint32_t a2, uint32_t a3,
                                         uint32_t b0, uint32_t b1) {
    asm volatile(
        "mma.sync.aligned.m16n8k16.row.col.f32.bf16.bf16.f32 "
        "{%0,%1,%2,%3}, {%4,%5,%6,%7}, {%8,%9}, {%0,%1,%2,%3};"
        : "+f"(d[0]), "+f"(d[1]), "+f"(d[2]), "+f"(d[3])
        : "r"(a0), "r"(a1), "r"(a2), "r"(a3), "r"(b0), "r"(b1));
}

// cp.async (sm_80 PTX) helpers — used by the recurrence only
__device__ __forceinline__ void cp16(uint32_t dst, const void* src) {
    asm volatile("cp.async.cg.shared.global [%0], [%1], 16;"
                 :: "r"(dst), "l"(src) : "memory");
}
#define CP_COMMIT() asm volatile("cp.async.commit_group;" ::: "memory")
#define CP_WAIT2()  asm volatile("cp.async.wait_group 2;" ::: "memory")

__device__ __forceinline__ uint32_t smem_u32(const void* p) {
    uint32_t a;
    asm("{ .reg .u64 t; cvta.to.shared.u64 t, %1; cvt.u32.u64 %0, t; }" : "=r"(a) : "l"(p));
    return a;
}

// ---------------------------------------------------------------------------
// Static device scratch. RULE (R13/R14 lesson): __device__ symbols are
// resolved ONLY inside device code; host passes flags, never symbol addresses.
//
// g_Af fragment-plane layout: per (mtile, kstep) block of 1024 B:
//   [hi: lane*16 -> uint4 {a0,a1,a2,a3}][lo at +512: same]
//   a0=(r, k0..k0+1)  a1=(r+8, k0..k0+1)  a2=(r, k0+8..9)  a3=(r+8, k0+8..9)
//   r = mtile*16 + lane>>2,  k0 = kstep*16 + (lane&3)*2,  mk = mtile*KS+kstep
// ---------------------------------------------------------------------------
__device__ float g_xz[(size_t)MTOT * G4];           // 256 MB  z-pre (natural layout)
__device__ float g_seq1[(size_t)MTOT * HH];         // 64 MB   layer-1 h sequence (fp32)
__device__ __align__(16) char g_Af[(size_t)(MTOT / 16) * 64 * 1024]; // 67 MB A fragments
__device__ __align__(16) uint4 g_Bw[(size_t)512 * 64 * 32];          // 16 MB packed W slots
__device__ __nv_bfloat16 g_hhi[2][BB * HH];         // h hi plane, ping-pong
__device__ __nv_bfloat16 g_hlo[2][BB * HH];         // h lo (residual) plane
__device__ unsigned g_bar8[8];                      // split grid-barrier counters

__global__ void zero_hc()
{
    int idx = blockIdx.x * blockDim.x + threadIdx.x;
    if (idx < BB * HH) {
        g_hhi[0][idx] = __float2bfloat16(0.f);
        g_hlo[0][idx] = __float2bfloat16(0.f);
    }
    if (idx < 8) g_bar8[idx] = 0u;
}

// ---------------------------------------------------------------------------
// pack_W: W fp32 [k][4096] -> B-fragment slots {bh0,bh1,bl0,bl1} (16 B/slot),
// slot index = (ntile*KS + kstep)*32 + lane. (proven in R15)
// ---------------------------------------------------------------------------
__global__ void pack_W(const float* __restrict__ W, int KS)
{
    size_t s = (size_t)blockIdx.x * 256 + threadIdx.x;
    if (s >= (size_t)512 * KS * 32) return;
    int lane = (int)(s & 31);
    size_t nk = s >> 5;                   // ntile*KS + kstep
    int kstep = (int)(nk % KS);
    int ntile = (int)(nk / KS);
    int n  = ntile * 8 + (lane >> 2);
    int k0 = kstep * 16 + (lane & 3) * 2;
    float v0 = W[(size_t)(k0    ) * G4 + n];
    float v1 = W[(size_t)(k0 + 1) * G4 + n];
    float v8 = W[(size_t)(k0 + 8) * G4 + n];
    float v9 = W[(size_t)(k0 + 9) * G4 + n];
    g_Bw[s] = make_uint4(pk_bf(v0, v1), pk_bf(v8, v9),
                         pk_bf(bf_res(v0), bf_res(v1)), pk_bf(bf_res(v8), bf_res(v9)));
}

// ---------------------------------------------------------------------------
// conv_A: fp32 A -> fragment planes g_Af, once per layer (kills the 32x
// per-CTA conversion duplication measured in R15's gemm profile).
// mode 0: A = x [b][t][d], m = t*64+b (K = 512)
// mode 1: A = g_seq1 row-major (K = 1024), resolved in device code
// One thread per lane-slot (writes hi uint4 + lo uint4).
// ---------------------------------------------------------------------------
__global__ void conv_A(const float* __restrict__ x, int KS, int mode)
{
    size_t s = (size_t)blockIdx.x * 256 + threadIdx.x;
    if (s >= (size_t)(MTOT / 16) * KS * 32) return;
    int lane = (int)(s & 31);
    size_t mk = s >> 5;                   // mtile*KS + kstep
    int kstep = (int)(mk % KS);
    int mtile = (int)(mk / KS);
    const int K = KS << 4;
    int r0 = mtile * 16 + (lane >> 2);
    int k0 = kstep * 16 + (lane & 3) * 2;
    const float *p0, *p1;
    if (mode == 0) {
        int m0 = r0, m1 = r0 + 8;
        p0 = x + ((size_t)((m0 & 63) * TT + (m0 >> 6))) * DD;
        p1 = x + ((size_t)((m1 & 63) * TT + (m1 >> 6))) * DD;
    } else {
        p0 = (const float*)g_seq1 + (size_t)r0 * K;
        p1 = (const float*)g_seq1 + (size_t)(r0 + 8) * K;
    }
    float2 v0 = *(const float2*)(p0 + k0);
    float2 v1 = *(const float2*)(p1 + k0);
    float2 v2 = *(const float2*)(p0 + k0 + 8);
    float2 v3 = *(const float2*)(p1 + k0 + 8);
    char* dst = g_Af + mk * 1024 + lane * 16;
    *(uint4*)dst = make_uint4(pk_bf(v0.x, v0.y), pk_bf(v1.x, v1.y),
                              pk_bf(v2.x, v2.y), pk_bf(v3.x, v3.y));
    *(uint4*)(dst + 512) =
        make_uint4(pk_bf(bf_res(v0.x), bf_res(v0.y)), pk_bf(bf_res(v1.x), bf_res(v1.y)),
                   pk_bf(bf_res(v2.x), bf_res(v2.y)), pk_bf(bf_res(v3.x), bf_res(v3.y)));
}

// ---------------------------------------------------------------------------
// gemm_mma_frag: g_xz[m][n] = sum_k A[m][k]*W[k][n] + bias[n] on mma.sync,
// 2-term bf16 split. Pure fragment consumption: 8 LDG.128 + 24 mma per
// warp-kstep, no conversion, no smem, no barriers.
// 512 thr, tile 128m x 128n per CTA: warp (mw=w&3, nw=w>>2) owns 32m x 32n.
// ---------------------------------------------------------------------------
__global__ __launch_bounds__(512) void gemm_mma_frag(const float* __restrict__ bias,
                                                     int KS)
{
    const int tid  = threadIdx.x;
    const int lane = tid & 31;
    const int w    = tid >> 5;
    const int mw   = w & 3;
    const int nw   = w >> 2;
    const int nblk = blockIdx.x;          // 0..31
    const int mblk = blockIdx.y;          // 0..127

    const char* Af = (const char*)g_Af;   // device-resolved

    float acc[2][4][4];
#pragma unroll
    for (int a = 0; a < 2; a++)
#pragma unroll
        for (int b = 0; b < 4; b++)
#pragma unroll
            for (int i = 0; i < 4; i++) acc[a][b][i] = 0.f;

    for (int kst = 0; kst < KS; kst++) {
        uint4 ah[2], al[2];
#pragma unroll
        for (int mt2 = 0; mt2 < 2; mt2++) {
            size_t mk = (size_t)(mblk * 8 + mw * 2 + mt2) * KS + kst;
            const char* ap = Af + mk * 1024 + lane * 16;
            ah[mt2] = __ldg((const uint4*)ap);
            al[mt2] = __ldg((const uint4*)(ap + 512));
        }
#pragma unroll
        for (int nt4 = 0; nt4 < 4; nt4++) {
            int ntile = nblk * 16 + nw * 4 + nt4;
            uint4 bv = __ldg(&g_Bw[((size_t)ntile * KS + kst) * 32 + lane]);
#pragma unroll
            for (int mt2 = 0; mt2 < 2; mt2++) {
                mma_bf16(acc[mt2][nt4], ah[mt2].x, ah[mt2].y, ah[mt2].z, ah[mt2].w, bv.x, bv.y);
                mma_bf16(acc[mt2][nt4], ah[mt2].x, ah[mt2].y, ah[mt2].z, ah[mt2].w, bv.z, bv.w);
                mma_bf16(acc[mt2][nt4], al[mt2].x, al[mt2].y, al[mt2].z, al[mt2].w, bv.x, bv.y);
            }
        }
    }

    // epilogue: bias + fp32 store (D fragment: d0,d1 = row; d2,d3 = row+8)
#pragma unroll
    for (int mt2 = 0; mt2 < 2; mt2++) {
        int row = mblk * 128 + mw * 32 + mt2 * 16 + (lane >> 2);
#pragma unroll
        for (int nt4 = 0; nt4 < 4; nt4++) {
            int col = nblk * 128 + nw * 32 + nt4 * 8 + (lane & 3) * 2;
            float b0 = __ldg(bias + col);
            float b1 = __ldg(bias + col + 1);
            *(float2*)(g_xz + (size_t)row * G4 + col) =
                make_float2(acc[mt2][nt4][0] + b0, acc[mt2][nt4][1] + b1);
            *(float2*)(g_xz + (size_t)(row + 8) * G4 + col) =
                make_float2(acc[mt2][nt4][2] + b0, acc[mt2][nt4][3] + b1);
        }
    }
}

// ---------------------------------------------------------------------------
// Persistent mma.sync recurrence — R11 version VERBATIM (best measured):
// CTA-wide coalesced cp.async staging, 4 stages, producer-side bf16 hi/lo
// h planes, fp32 seq1 stores for layer 0, 8-counter grid barrier.
// ---------------------------------------------------------------------------
#define OFF_UB     0
#define OFF_A      131072                // 4 bufs x (hi 9216 + lo 9216)
#define A_PLANE    9216
#define A_BUF      18432
#define SMEM_BYTES (131072 + 4 * 18432)  // 204,800 B

__global__ __launch_bounds__(512) void lstm_layer_mma(const float* __restrict__ U,
                                                      int layer)
{
    extern __shared__ char smc[];
    const int tid  = threadIdx.x;
    const int lane = tid & 31;
    const int w    = tid >> 5;          // 0..15
    const int mi   = w & 3;             // m-tile (16 rows)
    const int ks   = w >> 2;            // k-split 0..3
    const int u0   = blockIdx.x * 8;

    // ---- pack U slice into fragment-order smem, hi/lo interleaved 16B ----
    for (int s = tid; s < 8192; s += 512) {
        int ln  = s & 31;
        int nt  = (s >> 5) & 3;
        int kst = s >> 7;
        int gc  = (nt << 10) + u0 + (ln >> 2);
        int k0  = kst * 16 + (ln & 3) * 2;
        float v0 = U[(size_t)(k0    ) * G4 + gc];
        float v1 = U[(size_t)(k0 + 1) * G4 + gc];
        float v8 = U[(size_t)(k0 + 8) * G4 + gc];
        float v9 = U[(size_t)(k0 + 9) * G4 + gc];
        *(uint4*)(smc + OFF_UB + (size_t)s * 16) =
            make_uint4(pk_bf(v0, v1), pk_bf(v8, v9),
                       pk_bf(bf_res(v0), bf_res(v1)), pk_bf(bf_res(v8), bf_res(v9)));
    }

    const int row8 = tid >> 3;
    const int kseg = tid & 7;
    const uint32_t smbase = smem_u32(smc);
    const uint32_t st_hi  = smbase + OFF_A + (uint32_t)row8 * 144 + kseg * 16;
    const int      goff   = row8 * HH + kseg * 8;

    const int a_off = ((mi * 16 + (lane >> 2)) * 72 + ks * 16 + (lane & 3) * 2) * 2;

    float creg = 0.f;
    const int em = tid >> 3, ej = tid & 7;

    float* ZR = (float*)(smc + OFF_A);
    volatile unsigned* vb = g_bar8;

    __syncthreads();

    for (int t = 0; t < TT; t++) {
        const __nv_bfloat16* phi = g_hhi[t & 1] + goff;
        const __nv_bfloat16* plo = g_hlo[t & 1] + goff;

        const float* xzp = g_xz + ((size_t)t * BB + em) * G4 + u0 + ej;
        float x0 = __ldg(xzp);
        float x1 = __ldg(xzp + 1024);
        float x2 = __ldg(xzp + 2048);
        float x3 = __ldg(xzp + 3072);

#pragma unroll
        for (int pc = 0; pc < 3; pc++) {
            cp16(st_hi + pc * A_BUF,           phi + pc * 64);
            cp16(st_hi + pc * A_BUF + A_PLANE, plo + pc * 64);
            CP_COMMIT();
        }

        float d[4][4];
#pragma unroll
        for (int nt = 0; nt < 4; nt++)
#pragma unroll
            for (int i = 0; i < 4; i++) d[nt][i] = 0.f;

        for (int c = 0; c < 16; c++) {
            CP_WAIT2();
            __syncthreads();

            const char* ab = smc + OFF_A + (c & 3) * A_BUF + a_off;
            uint32_t ah0 = *(const uint32_t*)(ab);
            uint32_t ah1 = *(const uint32_t*)(ab + 1152);
            uint32_t ah2 = *(const uint32_t*)(ab + 16);
            uint32_t ah3 = *(const uint32_t*)(ab + 1168);
            uint32_t al0 = *(const uint32_t*)(ab + A_PLANE);
            uint32_t al1 = *(const uint32_t*)(ab + A_PLANE + 1152);
            uint32_t al2 = *(const uint32_t*)(ab + A_PLANE + 16);
            uint32_t al3 = *(const uint32_t*)(ab + A_PLANE + 1168);
#pragma unroll
            for (int nt = 0; nt < 4; nt++) {
                uint4 bv = *(const uint4*)(smc + OFF_UB +
                    (size_t)((((c * 4 + ks) * 4 + nt) * 32 + lane) * 16));
                mma_bf16(d[nt], ah0, ah1, ah2, ah3, bv.x, bv.y);
                mma_bf16(d[nt], ah0, ah1, ah2, ah3, bv.z, bv.w);
                mma_bf16(d[nt], al0, al1, al2, al3, bv.x, bv.y);
            }

            if (c < 13) {
                cp16(st_hi + ((c + 3) & 3) * A_BUF,           phi + (c + 3) * 64);
                cp16(st_hi + ((c + 3) & 3) * A_BUF + A_PLANE, plo + (c + 3) * 64);
            }
            CP_COMMIT();
        }
        __syncthreads();

        {
            int zw = ks * 2176 + (mi * 16 + (lane >> 2)) * 34 + (lane & 3) * 2;
#pragma unroll
            for (int nt = 0; nt < 4; nt++) {
                *(float2*)&ZR[zw + nt * 8]          = make_float2(d[nt][0], d[nt][1]);
                *(float2*)&ZR[zw + nt * 8 + 8 * 34] = make_float2(d[nt][2], d[nt][3]);
            }
        }
        __syncthreads();
        {
            float z[4];
#pragma unroll
            for (int g = 0; g < 4; g++) {
                int zc = em * 34 + g * 8 + ej;
                z[g] = ZR[zc] + ZR[zc + 2176] + ZR[zc + 4352] + ZR[zc + 6528];
            }
            float zi = z[0] + x0;
            float zf = z[1] + x1;
            float zg = z[2] + x2;
            float zo = z[3] + x3;
            float si = 1.f / (1.f + __expf(-zi));
            float sf = 1.f / (1.f + __expf(-zf));
            float so = 1.f / (1.f + __expf(-zo));
            float tg = tanhf(zg);
            float cn = sf * creg + si * tg;
            creg = cn;
            float hn = so * tanhf(cn);
            __nv_bfloat16 hb = __float2bfloat16_rn(hn);
            __nv_bfloat16 lb = __float2bfloat16_rn(hn - __bfloat162float(hb));
            int idx = em * HH + u0 + ej;
            g_hhi[(t + 1) & 1][idx] = hb;
            g_hlo[(t + 1) & 1][idx] = lb;
            if (layer == 0)
                g_seq1[(size_t)t * BB * HH + idx] = hn;
        }

        if (t < TT - 1) {
            __threadfence();
            __syncthreads();
            if (tid == 0) atomicAdd(&g_bar8[blockIdx.x & 7], 1u);
            unsigned target = (unsigned)(t + 1) * 16u;
            if (tid < 8) { while (vb[tid] < target) { } }
            __syncthreads();
        }
    }
}

// ---------------------------------------------------------------------------
// Final dense: h_last reconstructed from hi+lo planes (buf 0, T even)
// ---------------------------------------------------------------------------
__global__ void dense_out(const float* __restrict__ Wd, const float* __restrict__ bd,
                          float* __restrict__ out)
{
    int b = blockIdx.x;
    int o = threadIdx.x;
    const __nv_bfloat16* hi = g_hhi[0] + (size_t)b * HH;
    const __nv_bfloat16* lo = g_hlo[0] + (size_t)b * HH;
    float acc = bd[o];
#pragma unroll 8
    for (int k = 0; k < HH; k++) {
        float h = __bfloat162float(hi[k]) + __bfloat162float(lo[k]);
        acc += h * Wd[(size_t)k * OO + o];
    }
    out[(size_t)b * OO + o] = acc;
}

// ---------------------------------------------------------------------------
// Launch sequence (gemm_mma_frag L1 at index 3 for the ncu capture).
// __device__ symbols are never passed as arguments from host.
// ---------------------------------------------------------------------------
extern "C" void kernel_launch(void* const* d_in, const int* in_sizes, int n_in,
                              void* d_out, int out_size)
{
    const float* x  = (const float*)d_in[0];
    const float* W1 = (const float*)d_in[1];
    const float* U1 = (const float*)d_in[2];
    const float* b1 = (const float*)d_in[3];
    const float* W2 = (const float*)d_in[4];
    const float* U2 = (const float*)d_in[5];
    const float* b2 = (const float*)d_in[6];
    const float* Wd = (const float*)d_in[7];
    const float* bd = (const float*)d_in[8];
    float* out = (float*)d_out;

    cudaFuncSetAttribute(lstm_layer_mma,
                         cudaFuncAttributeMaxDynamicSharedMemorySize, SMEM_BYTES);

    dim3 gg(32, 128);
    const int convA1_blocks = (int)(((size_t)(MTOT / 16) * 32 * 32 + 255) / 256);
    const int convA2_blocks = (int)(((size_t)(MTOT / 16) * 64 * 32 + 255) / 256);

    // ---- Layer 1 ----
    pack_W<<<(int)(((size_t)512 * 32 * 32 + 255) / 256), 256>>>(W1, 32);     // 0
    conv_A<<<convA1_blocks, 256>>>(x, 32, 0);                                // 1
    zero_hc<<<(BB * HH + 255) / 256, 256>>>();                               // 2
    gemm_mma_frag<<<gg, 512>>>(b1, 32);                                      // 3 <- profiled
    lstm_layer_mma<<<128, 512, SMEM_BYTES>>>(U1, 0);                         // 4

    // ---- Layer 2 ----
    pack_W<<<(int)(((size_t)512 * 64 * 32 + 255) / 256), 256>>>(W2, 64);     // 5
    conv_A<<<convA2_blocks, 256>>>(nullptr, 64, 1);                          // 6
    zero_hc<<<(BB * HH + 255) / 256, 256>>>();                               // 7
    gemm_mma_frag<<<gg, 512>>>(b2, 64);                                      // 8
    lstm_layer_mma<<<128, 512, SMEM_BYTES>>>(U2, 1);                         // 9

    // ---- Dense head ----
    dense_out<<<BB, OO>>>(Wd, bd, out);                                      // 10
}